// round 9
// baseline (speedup 1.0000x reference)
#include <cuda_runtime.h>
#include <cuda_fp16.h>
#include <cstdint>

#define KTAGS 256
#define NTH   256
#define SMAX  1024
#define LN2F  0.69314718055994531f

// ET column-pair-major: d_ETp[c*128 + i] = half2( exp(T[2i][c]), exp(T[2i+1][c]) )
__device__ __half2 d_ETp[KTAGS * (KTAGS / 2)];

__global__ void crf_prep(const float* __restrict__ trans) {
    int idx = blockIdx.x * blockDim.x + threadIdx.x;
    if (idx < KTAGS * (KTAGS / 2)) {
        int c = idx >> 7, i = idx & 127;
        float lo = expf(trans[(2 * i)     * KTAGS + c]);
        float hi = expf(trans[(2 * i + 1) * KTAGS + c]);
        d_ETp[idx] = __floats2half2_rn(lo, hi);
    }
}

__device__ __forceinline__ __half2 u2h(unsigned int u) { __half2 h; *(unsigned int*)&h = u; return h; }

__global__ __launch_bounds__(NTH, 1)
void crf_main(const float* __restrict__ emissions,
              const int* __restrict__ targets,
              const int* __restrict__ masks,
              const float* __restrict__ start_t,
              const float* __restrict__ end_t,
              const float* __restrict__ trans,
              float* __restrict__ out,
              int S)
{
    __shared__ __align__(16) unsigned int pvec[2][KTAGS / 2];  // p as half2, double-buffered
    __shared__ float pz[2];                                    // fp32 proxy (thread 0's p)
    __shared__ float red[8];
    __shared__ float rscr[NTH], cscr[NTH];
    __shared__ float num_smem;
    __shared__ int ms[SMAX];

    const int tid = threadIdx.x, b = blockIdx.x;
    const int lane = tid & 31, wid = tid >> 5;
    const int c = tid;                                  // my output column (tag)
    const int own = 4 * wid;                            // my warp's own uint4 base in pvec

    const float* emb  = emissions + (size_t)b * S * KTAGS;
    const int*   tg   = targets  + (size_t)b * S;
    const int*   mrow = masks    + (size_t)b * S;

    // ---- ET column c into registers: 128 half2 as 32 uint4 ----
    uint4 et4[32];
    {
        const uint4* etg = (const uint4*)(d_ETp + (size_t)c * 128);
        #pragma unroll
        for (int k = 0; k < 32; k++) et4[k] = etg[k];
    }

    // ---- masks into SMEM ----
    for (int t = tid; t < S && t < SMAX; t += NTH) ms[t] = mrow[t];

    // ---- Numerator ----
    float npart = 0.f; int cnt = 0;
    for (int t = tid; t < S; t += NTH) {
        int m = mrow[t] != 0; cnt += m;
        if (t >= 1 && m) {
            int pv = tg[t - 1], cu = tg[t];
            npart += trans[pv * KTAGS + cu] + emb[(size_t)t * KTAGS + cu];
        }
    }
    rscr[tid] = npart; cscr[tid] = (float)cnt;
    __syncthreads();
    if (tid == 0) {
        float tot = 0.f, cc = 0.f;
        for (int i = 0; i < NTH; i++) { tot += rscr[i]; cc += cscr[i]; }
        int seq_end = (int)cc - 1; int t0 = tg[0];
        num_smem = tot + start_t[t0] + emb[t0] + end_t[tg[seq_end]];
    }

    // ---- Init (t = 0): exact max-normalization + exact Sp once ----
    float s0 = start_t[c] + emb[c];
    float m = s0;
    #pragma unroll
    for (int o = 16; o > 0; o >>= 1) m = fmaxf(m, __shfl_xor_sync(0xffffffffu, m, o));
    if (lane == 0) red[wid] = m;
    __syncthreads();
    float M = red[0];
    #pragma unroll
    for (int w = 1; w < 8; w++) M = fmaxf(M, red[w]);
    float p = __expf(s0 - M);
    int ktot = 0;

    ((__half*)pvec[0])[c] = __float2half(p);
    float psum = p;
    #pragma unroll
    for (int o = 16; o > 0; o >>= 1) psum += __shfl_xor_sync(0xffffffffu, psum, o);
    if (lane == 0) red[wid] = psum;
    __syncthreads();
    if (tid == 0) {
        float Sp = 0.f;
        #pragma unroll
        for (int w = 0; w < 8; w++) Sp += red[w];
        pz[0] = Sp * (1.0f / 256.0f);
    }

    // emission pipeline: ee = exp(e_t) for t=1, eraw = raw e for t=2
    float ee   = __expf(emb[(size_t)((1 < S) ? 1 : 0) * KTAGS + c]);
    float eraw = emb[(size_t)((2 < S) ? 2 : (S - 1)) * KTAGS + c];

    // ---- prepass for step 1: own-warp section of pvec[0] (no CTA barrier needed) ----
    __half2 a0, a1, a2, a3, a4, a5, a6, a7;
    {
        const uint4* pv = (const uint4*)pvec[0];
        uint4 q0 = pv[own],     q1 = pv[own + 1];
        uint4 q2 = pv[own + 2], q3 = pv[own + 3];
        a0 = __hmul2(u2h(et4[own].x),     u2h(q0.x));
        a1 = __hmul2(u2h(et4[own].y),     u2h(q0.y));
        a2 = __hmul2(u2h(et4[own].z),     u2h(q0.z));
        a3 = __hmul2(u2h(et4[own].w),     u2h(q0.w));
        a4 = __hmul2(u2h(et4[own + 1].x), u2h(q1.x));
        a5 = __hmul2(u2h(et4[own + 1].y), u2h(q1.y));
        a6 = __hmul2(u2h(et4[own + 1].z), u2h(q1.z));
        a7 = __hmul2(u2h(et4[own + 1].w), u2h(q1.w));
        a0 = __hfma2(u2h(et4[own + 2].x), u2h(q2.x), a0);
        a1 = __hfma2(u2h(et4[own + 2].y), u2h(q2.y), a1);
        a2 = __hfma2(u2h(et4[own + 2].z), u2h(q2.z), a2);
        a3 = __hfma2(u2h(et4[own + 2].w), u2h(q2.w), a3);
        a4 = __hfma2(u2h(et4[own + 3].x), u2h(q3.x), a4);
        a5 = __hfma2(u2h(et4[own + 3].y), u2h(q3.y), a5);
        a6 = __hfma2(u2h(et4[own + 3].z), u2h(q3.z), a6);
        a7 = __hfma2(u2h(et4[own + 3].w), u2h(q3.w), a7);
    }

    // ---- Forward recursion: one barrier per step ----
    for (int t = 1; t < S; t++) {
        const int par = t & 1, pre = par ^ 1;
        __syncthreads();

        int tn = (t + 2 < S) ? (t + 2) : (S - 1);
        float eraw2 = emb[(size_t)tn * KTAGS + c];
        int msk = (t < SMAX) ? ms[t] : mrow[t];

        // lag-1 proxy normalizer: single broadcast LDS + bit ops
        float P = pz[pre];
        unsigned int sb = __float_as_uint(P);
        int ke = (int)(sb >> 23) - 118;                                   // ilogb+9
        float sf = __uint_as_float((unsigned int)(245 - (int)(sb >> 23)) << 23);  // 2^-ke

        // matvec remainder: 28 uint4s, rotated so the 2 warps/SMSP de-correlate
        const uint4* pv = (const uint4*)pvec[pre];
        #pragma unroll
        for (int j = 4; j < 32; j += 2) {
            int k0 = (own + j) & 31;
            int k1 = (own + j + 1) & 31;
            uint4 q0 = pv[k0];
            uint4 q1 = pv[k1];
            a0 = __hfma2(u2h(et4[k0].x), u2h(q0.x), a0);
            a1 = __hfma2(u2h(et4[k0].y), u2h(q0.y), a1);
            a2 = __hfma2(u2h(et4[k0].z), u2h(q0.z), a2);
            a3 = __hfma2(u2h(et4[k0].w), u2h(q0.w), a3);
            a4 = __hfma2(u2h(et4[k1].x), u2h(q1.x), a4);
            a5 = __hfma2(u2h(et4[k1].y), u2h(q1.y), a5);
            a6 = __hfma2(u2h(et4[k1].z), u2h(q1.z), a6);
            a7 = __hfma2(u2h(et4[k1].w), u2h(q1.w), a7);
        }
        // fold: 8 -> 1 half2, then single half add + one convert
        __half2 sT = __hadd2(__hadd2(__hadd2(a0, a1), __hadd2(a2, a3)),
                             __hadd2(__hadd2(a4, a5), __hadd2(a6, a7)));
        float ssum = __half2float(__hadd(__low2half(sT), __high2half(sT)));

        float q = ssum * ee;
        if (msk) { p = q * sf; ktot += ke; }

        ((__half*)pvec[par])[c] = __float2half(p);
        if (tid == 0) pz[par] = p;
        __syncwarp();

        // prepass for step t+1 on own-warp section of pvec[par]
        {
            const uint4* pw = (const uint4*)pvec[par];
            uint4 q0 = pw[own],     q1 = pw[own + 1];
            uint4 q2 = pw[own + 2], q3 = pw[own + 3];
            a0 = __hmul2(u2h(et4[own].x),     u2h(q0.x));
            a1 = __hmul2(u2h(et4[own].y),     u2h(q0.y));
            a2 = __hmul2(u2h(et4[own].z),     u2h(q0.z));
            a3 = __hmul2(u2h(et4[own].w),     u2h(q0.w));
            a4 = __hmul2(u2h(et4[own + 1].x), u2h(q1.x));
            a5 = __hmul2(u2h(et4[own + 1].y), u2h(q1.y));
            a6 = __hmul2(u2h(et4[own + 1].z), u2h(q1.z));
            a7 = __hmul2(u2h(et4[own + 1].w), u2h(q1.w));
            a0 = __hfma2(u2h(et4[own + 2].x), u2h(q2.x), a0);
            a1 = __hfma2(u2h(et4[own + 2].y), u2h(q2.y), a1);
            a2 = __hfma2(u2h(et4[own + 2].z), u2h(q2.z), a2);
            a3 = __hfma2(u2h(et4[own + 2].w), u2h(q2.w), a3);
            a4 = __hfma2(u2h(et4[own + 3].x), u2h(q3.x), a4);
            a5 = __hfma2(u2h(et4[own + 3].y), u2h(q3.y), a5);
            a6 = __hfma2(u2h(et4[own + 3].z), u2h(q3.z), a6);
            a7 = __hfma2(u2h(et4[own + 3].w), u2h(q3.w), a7);
        }

        // off-critical-path: emission exp for step t+1
        ee = __expf(eraw);
        eraw = eraw2;
    }

    // ---- Final: denominator = M + ktot*ln2 + log(Sigma p * exp(end)) ----
    float v = p * __expf(end_t[c]);
    #pragma unroll
    for (int o = 16; o > 0; o >>= 1) v += __shfl_xor_sync(0xffffffffu, v, o);
    if (lane == 0) red[wid] = v;
    __syncthreads();
    if (tid == 0) {
        float tot = 0.f;
        #pragma unroll
        for (int w = 0; w < 8; w++) tot += red[w];
        out[b] = num_smem - (M + (float)ktot * LN2F + __logf(tot));
    }
}

extern "C" void kernel_launch(void* const* d_in, const int* in_sizes, int n_in,
                              void* d_out, int out_size) {
    const float* emissions = (const float*)d_in[0];
    const int*   targets   = (const int*)d_in[1];
    const int*   masks     = (const int*)d_in[2];
    const float* start_t   = (const float*)d_in[3];
    const float* end_t     = (const float*)d_in[4];
    const float* trans     = (const float*)d_in[5];
    float*       out       = (float*)d_out;

    int B = out_size;
    int S = in_sizes[1] / B;

    crf_prep<<<(KTAGS * (KTAGS / 2) + 255) / 256, 256>>>(trans);
    crf_main<<<B, NTH>>>(emissions, targets, masks, start_t, end_t, trans, out, S);
}

// round 10
// speedup vs baseline: 2.2703x; 2.2703x over previous
#include <cuda_runtime.h>
#include <cuda_fp16.h>
#include <cstdint>

#define KTAGS 256
#define NTH   256
#define SMAX  1024
#define LN2F  0.69314718055994531f

// ET column-pair-major: d_ETp[c*128 + i] = half2( exp(T[2i][c]), exp(T[2i+1][c]) )
__device__ __half2 d_ETp[KTAGS * (KTAGS / 2)];

__global__ void crf_prep(const float* __restrict__ trans) {
    int idx = blockIdx.x * blockDim.x + threadIdx.x;
    if (idx < KTAGS * (KTAGS / 2)) {
        int c = idx >> 7, i = idx & 127;
        float lo = expf(trans[(2 * i)     * KTAGS + c]);
        float hi = expf(trans[(2 * i + 1) * KTAGS + c]);
        d_ETp[idx] = __floats2half2_rn(lo, hi);
    }
}

__device__ __forceinline__ __half2 u2h(unsigned int u) { __half2 h; *(unsigned int*)&h = u; return h; }

__global__ __launch_bounds__(NTH, 1)
void crf_main(const float* __restrict__ emissions,
              const int* __restrict__ targets,
              const int* __restrict__ masks,
              const float* __restrict__ start_t,
              const float* __restrict__ end_t,
              const float* __restrict__ trans,
              float* __restrict__ out,
              int S)
{
    __shared__ __align__(16) unsigned int pvec[2][KTAGS / 2];  // p as half2, double-buffered
    __shared__ float pz[2];                                    // fp32 proxy (thread 0's p)
    __shared__ float red[8];
    __shared__ float rscr[NTH], cscr[NTH];
    __shared__ float num_smem;
    __shared__ int ms[SMAX];

    const int tid = threadIdx.x, b = blockIdx.x;
    const int lane = tid & 31, wid = tid >> 5;
    const int c = tid;                                  // my output column (tag)
    const int own = 4 * wid;                            // my warp's own uint4 base in pvec

    const float* emb  = emissions + (size_t)b * S * KTAGS;
    const int*   tg   = targets  + (size_t)b * S;
    const int*   mrow = masks    + (size_t)b * S;

    // ---- ET column c into registers, PERMUTED at load time:
    //      et4[j] holds ET row-block (own+j)&31, so all register indices stay static.
    uint4 et4[32];
    {
        const uint4* etg = (const uint4*)(d_ETp + (size_t)c * 128);
        #pragma unroll
        for (int j = 0; j < 32; j++) et4[j] = etg[(own + j) & 31];
    }

    // ---- masks into SMEM ----
    for (int t = tid; t < S && t < SMAX; t += NTH) ms[t] = mrow[t];

    // ---- Numerator ----
    float npart = 0.f; int cnt = 0;
    for (int t = tid; t < S; t += NTH) {
        int m = mrow[t] != 0; cnt += m;
        if (t >= 1 && m) {
            int pv = tg[t - 1], cu = tg[t];
            npart += trans[pv * KTAGS + cu] + emb[(size_t)t * KTAGS + cu];
        }
    }
    rscr[tid] = npart; cscr[tid] = (float)cnt;
    __syncthreads();
    if (tid == 0) {
        float tot = 0.f, cc = 0.f;
        for (int i = 0; i < NTH; i++) { tot += rscr[i]; cc += cscr[i]; }
        int seq_end = (int)cc - 1; int t0 = tg[0];
        num_smem = tot + start_t[t0] + emb[t0] + end_t[tg[seq_end]];
    }

    // ---- Init (t = 0): exact max-normalization + exact Sp once ----
    float s0 = start_t[c] + emb[c];
    float m = s0;
    #pragma unroll
    for (int o = 16; o > 0; o >>= 1) m = fmaxf(m, __shfl_xor_sync(0xffffffffu, m, o));
    if (lane == 0) red[wid] = m;
    __syncthreads();
    float M = red[0];
    #pragma unroll
    for (int w = 1; w < 8; w++) M = fmaxf(M, red[w]);
    float p = __expf(s0 - M);
    int ktot = 0;

    ((__half*)pvec[0])[c] = __float2half(p);
    float psum = p;
    #pragma unroll
    for (int o = 16; o > 0; o >>= 1) psum += __shfl_xor_sync(0xffffffffu, psum, o);
    if (lane == 0) red[wid] = psum;
    __syncthreads();
    if (tid == 0) {
        float Sp = 0.f;
        #pragma unroll
        for (int w = 0; w < 8; w++) Sp += red[w];
        pz[0] = Sp * (1.0f / 256.0f);
    }

    // emission pipeline: ee = exp(e_t) for t=1, eraw = raw e for t=2
    float ee   = __expf(emb[(size_t)((1 < S) ? 1 : 0) * KTAGS + c]);
    float eraw = emb[(size_t)((2 < S) ? 2 : (S - 1)) * KTAGS + c];

    const unsigned int* pz_ok = (const unsigned int*)pz;  // silence unused warnings pattern

    // ---- prepass for step 1: own-warp section (pv blocks own..own+3 = et4[0..3]) ----
    __half2 a0, a1, a2, a3, a4, a5, a6, a7;
    {
        const uint4* pv = (const uint4*)pvec[0];
        uint4 q0 = pv[own],     q1 = pv[own + 1];
        uint4 q2 = pv[own + 2], q3 = pv[own + 3];
        a0 = __hmul2(u2h(et4[0].x), u2h(q0.x));
        a1 = __hmul2(u2h(et4[0].y), u2h(q0.y));
        a2 = __hmul2(u2h(et4[0].z), u2h(q0.z));
        a3 = __hmul2(u2h(et4[0].w), u2h(q0.w));
        a4 = __hmul2(u2h(et4[1].x), u2h(q1.x));
        a5 = __hmul2(u2h(et4[1].y), u2h(q1.y));
        a6 = __hmul2(u2h(et4[1].z), u2h(q1.z));
        a7 = __hmul2(u2h(et4[1].w), u2h(q1.w));
        a0 = __hfma2(u2h(et4[2].x), u2h(q2.x), a0);
        a1 = __hfma2(u2h(et4[2].y), u2h(q2.y), a1);
        a2 = __hfma2(u2h(et4[2].z), u2h(q2.z), a2);
        a3 = __hfma2(u2h(et4[2].w), u2h(q2.w), a3);
        a4 = __hfma2(u2h(et4[3].x), u2h(q3.x), a4);
        a5 = __hfma2(u2h(et4[3].y), u2h(q3.y), a5);
        a6 = __hfma2(u2h(et4[3].z), u2h(q3.z), a6);
        a7 = __hfma2(u2h(et4[3].w), u2h(q3.w), a7);
    }
    (void)pz_ok;

    // ---- Forward recursion: one barrier per step ----
    for (int t = 1; t < S; t++) {
        const int par = t & 1, pre = par ^ 1;
        __syncthreads();

        int tn = (t + 2 < S) ? (t + 2) : (S - 1);
        float eraw2 = emb[(size_t)tn * KTAGS + c];
        int msk = (t < SMAX) ? ms[t] : mrow[t];

        // lag-1 proxy normalizer: single broadcast LDS + bit ops
        float P = pz[pre];
        unsigned int sb = __float_as_uint(P);
        int ke = (int)(sb >> 23) - 118;                                   // ilogb+9
        float sf = __uint_as_float((unsigned int)(245 - (int)(sb >> 23)) << 23);  // 2^-ke

        // matvec remainder: 28 blocks, warp-rotated pv addresses, static et4 indices
        const uint4* pv = (const uint4*)pvec[pre];
        #pragma unroll
        for (int j = 4; j < 32; j += 2) {
            uint4 q0 = pv[(own + j) & 31];
            uint4 q1 = pv[(own + j + 1) & 31];
            a0 = __hfma2(u2h(et4[j].x),     u2h(q0.x), a0);
            a1 = __hfma2(u2h(et4[j].y),     u2h(q0.y), a1);
            a2 = __hfma2(u2h(et4[j].z),     u2h(q0.z), a2);
            a3 = __hfma2(u2h(et4[j].w),     u2h(q0.w), a3);
            a4 = __hfma2(u2h(et4[j + 1].x), u2h(q1.x), a4);
            a5 = __hfma2(u2h(et4[j + 1].y), u2h(q1.y), a5);
            a6 = __hfma2(u2h(et4[j + 1].z), u2h(q1.z), a6);
            a7 = __hfma2(u2h(et4[j + 1].w), u2h(q1.w), a7);
        }
        // fold: 8 -> 1 half2, then single half add + one convert
        __half2 sT = __hadd2(__hadd2(__hadd2(a0, a1), __hadd2(a2, a3)),
                             __hadd2(__hadd2(a4, a5), __hadd2(a6, a7)));
        float ssum = __half2float(__hadd(__low2half(sT), __high2half(sT)));

        float q = ssum * ee;
        if (msk) { p = q * sf; ktot += ke; }

        ((__half*)pvec[par])[c] = __float2half(p);
        if (tid == 0) pz[par] = p;
        __syncwarp();

        // prepass for step t+1 on own-warp section of pvec[par] (et4[0..3], static)
        {
            const uint4* pw = (const uint4*)pvec[par];
            uint4 q0 = pw[own],     q1 = pw[own + 1];
            uint4 q2 = pw[own + 2], q3 = pw[own + 3];
            a0 = __hmul2(u2h(et4[0].x), u2h(q0.x));
            a1 = __hmul2(u2h(et4[0].y), u2h(q0.y));
            a2 = __hmul2(u2h(et4[0].z), u2h(q0.z));
            a3 = __hmul2(u2h(et4[0].w), u2h(q0.w));
            a4 = __hmul2(u2h(et4[1].x), u2h(q1.x));
            a5 = __hmul2(u2h(et4[1].y), u2h(q1.y));
            a6 = __hmul2(u2h(et4[1].z), u2h(q1.z));
            a7 = __hmul2(u2h(et4[1].w), u2h(q1.w));
            a0 = __hfma2(u2h(et4[2].x), u2h(q2.x), a0);
            a1 = __hfma2(u2h(et4[2].y), u2h(q2.y), a1);
            a2 = __hfma2(u2h(et4[2].z), u2h(q2.z), a2);
            a3 = __hfma2(u2h(et4[2].w), u2h(q2.w), a3);
            a4 = __hfma2(u2h(et4[3].x), u2h(q3.x), a4);
            a5 = __hfma2(u2h(et4[3].y), u2h(q3.y), a5);
            a6 = __hfma2(u2h(et4[3].z), u2h(q3.z), a6);
            a7 = __hfma2(u2h(et4[3].w), u2h(q3.w), a7);
        }

        // off-critical-path: emission exp for step t+1
        ee = __expf(eraw);
        eraw = eraw2;
    }

    // ---- Final: denominator = M + ktot*ln2 + log(Sigma p * exp(end)) ----
    float v = p * __expf(end_t[c]);
    #pragma unroll
    for (int o = 16; o > 0; o >>= 1) v += __shfl_xor_sync(0xffffffffu, v, o);
    if (lane == 0) red[wid] = v;
    __syncthreads();
    if (tid == 0) {
        float tot = 0.f;
        #pragma unroll
        for (int w = 0; w < 8; w++) tot += red[w];
        out[b] = num_smem - (M + (float)ktot * LN2F + __logf(tot));
    }
}

extern "C" void kernel_launch(void* const* d_in, const int* in_sizes, int n_in,
                              void* d_out, int out_size) {
    const float* emissions = (const float*)d_in[0];
    const int*   targets   = (const int*)d_in[1];
    const int*   masks     = (const int*)d_in[2];
    const float* start_t   = (const float*)d_in[3];
    const float* end_t     = (const float*)d_in[4];
    const float* trans     = (const float*)d_in[5];
    float*       out       = (float*)d_out;

    int B = out_size;
    int S = in_sizes[1] / B;

    crf_prep<<<(KTAGS * (KTAGS / 2) + 255) / 256, 256>>>(trans);
    crf_main<<<B, NTH>>>(emissions, targets, masks, start_t, end_t, trans, out, S);
}